// round 16
// baseline (speedup 1.0000x reference)
#include <cuda_runtime.h>
#include <cuda_fp16.h>
#include <cstdint>
#include <math.h>

// Problem constants
#define BB 4
#define NN 2048
#define DD 512
#define HH 8
#define HD 64
#define NC 2048
#define RR (BB*NN)

// Scratch (device globals; no allocation allowed)
__device__ __half g_xnh[(size_t)RR * DD];   // half: layernorm(x); later o_input
__device__ __half g_mmh[(size_t)RR * NC];   // half: silu(xn @ uvqk) [u|v|q|k]
__device__ __half g_wh [(size_t)NC * DD];   // half: uvqk transposed [n][k]
__device__ __half g_owh[(size_t)DD * DD];   // half: o_weight [n][k]
__device__ __half g_ath[(size_t)RR * DD];   // half attention output

// silu on a packed pair via tanh.approx.f16x2 (1 MUFU per 2 values)
__device__ __forceinline__ uint32_t silu_h2(float a, float b) {
    __half2 s = __floats2half2_rn(a, b);
    const __half2 hhalf = __floats2half2_rn(0.5f, 0.5f);
    __half2 hs = __hmul2(s, hhalf);
    uint32_t hsu = *(uint32_t*)&hs;
    uint32_t t;
    asm("tanh.approx.f16x2 %0, %1;" : "=r"(t) : "r"(hsu));
    __half2 th = *(__half2*)&t;
    __half2 sig = __hfma2(th, hhalf, hhalf);
    __half2 o = __hmul2(s, sig);
    return *(uint32_t*)&o;
}

__device__ __forceinline__ uint32_t smem_u32(const void* p) {
    uint32_t a;
    asm("{ .reg .u64 t; cvta.to.shared.u64 t, %1; cvt.u32.u64 %0, t; }"
        : "=r"(a) : "l"(p));
    return a;
}

__device__ __forceinline__ void ldmA(uint32_t* a, uint32_t addr) {
    asm volatile("ldmatrix.sync.aligned.m8n8.x4.shared.b16 {%0,%1,%2,%3}, [%4];"
                 : "=r"(a[0]), "=r"(a[1]), "=r"(a[2]), "=r"(a[3]) : "r"(addr));
}

__device__ __forceinline__ void ldmT(uint32_t* a, uint32_t addr) {
    asm volatile("ldmatrix.sync.aligned.m8n8.x4.trans.shared.b16 {%0,%1,%2,%3}, [%4];"
                 : "=r"(a[0]), "=r"(a[1]), "=r"(a[2]), "=r"(a[3]) : "r"(addr));
}

// fp16 mma, fp32 accumulate: D += A(16x16) * B(16x8)
__device__ __forceinline__ void mma_f16(float* d, const uint32_t* a,
                                        uint32_t b0, uint32_t b1) {
    asm volatile(
        "mma.sync.aligned.m16n8k16.row.col.f32.f16.f16.f32 "
        "{%0,%1,%2,%3},{%4,%5,%6,%7},{%8,%9},{%0,%1,%2,%3};"
        : "+f"(d[0]), "+f"(d[1]), "+f"(d[2]), "+f"(d[3])
        : "r"(a[0]), "r"(a[1]), "r"(a[2]), "r"(a[3]), "r"(b0), "r"(b1));
}

__device__ __forceinline__ void cp16(uint32_t dst, const void* src) {
    asm volatile("cp.async.cg.shared.global [%0], [%1], 16;" :: "r"(dst), "l"(src));
}
#define CP_COMMIT() asm volatile("cp.async.commit_group;" ::: "memory")
#define CP_WAIT(n)  asm volatile("cp.async.wait_group %0;" :: "n"(n) : "memory")

// ldmatrix-x4 per-lane byte offset for a 16x16-half A block, stride in halfs
__device__ __forceinline__ uint32_t ldm_off_h(int lane, int stride_halfs) {
    int r = (lane & 7) + ((lane >> 3) & 1) * 8;
    int c16 = (lane >> 4);
    return (uint32_t)(r * stride_halfs * 2 + c16 * 16);
}

// ldmatrix-x4 per-lane byte offset for B (K-major [n][k]): 2 n-frags x k16.
__device__ __forceinline__ uint32_t ldm_off_b(int lane, int stride_halfs) {
    int r = lane & 7;
    int m = lane >> 3;
    return (uint32_t)(((m >> 1) * 8 + r) * stride_halfs * 2 + (m & 1) * 16);
}

// ---------------------------------------------------------------------------
// LayerNorm: fp32 math, half output
// ---------------------------------------------------------------------------
__global__ void ln_kernel(const float* __restrict__ x) {
    int row = blockIdx.x;
    int t = threadIdx.x;
    float4 v = ((const float4*)(x + (size_t)row * DD))[t];
    float s  = v.x + v.y + v.z + v.w;
    float s2 = v.x*v.x + v.y*v.y + v.z*v.z + v.w*v.w;
#pragma unroll
    for (int o = 16; o > 0; o >>= 1) {
        s  += __shfl_xor_sync(0xffffffffu, s,  o);
        s2 += __shfl_xor_sync(0xffffffffu, s2, o);
    }
    __shared__ float sh[8];
    if ((t & 31) == 0) { sh[t >> 5] = s; sh[4 + (t >> 5)] = s2; }
    __syncthreads();
    s  = sh[0] + sh[1] + sh[2] + sh[3];
    s2 = sh[4] + sh[5] + sh[6] + sh[7];
    float mu  = s * (1.0f / DD);
    float var = fmaxf(s2 * (1.0f / DD) - mu * mu, 0.0f);
    float r   = rsqrtf(var + 1e-6f);
    __half2 h0 = __floats2half2_rn((v.x - mu) * r, (v.y - mu) * r);
    __half2 h1 = __floats2half2_rn((v.z - mu) * r, (v.w - mu) * r);
    ((__half2*)(g_xnh + (size_t)row * DD))[2 * t]     = h0;
    ((__half2*)(g_xnh + (size_t)row * DD))[2 * t + 1] = h1;
}

// Gated LN: reads half attention output, fp32 stats, half result
__global__ void gated_ln_kernel() {
    int row = blockIdx.x;
    int t = threadIdx.x;
    __half2 a01 = ((const __half2*)(g_ath + (size_t)row * DD))[2 * t];
    __half2 a23 = ((const __half2*)(g_ath + (size_t)row * DD))[2 * t + 1];
    float2 f0 = __half22float2(a01), f1 = __half22float2(a23);
    float s  = f0.x + f0.y + f1.x + f1.y;
    float s2 = f0.x*f0.x + f0.y*f0.y + f1.x*f1.x + f1.y*f1.y;
#pragma unroll
    for (int o = 16; o > 0; o >>= 1) {
        s  += __shfl_xor_sync(0xffffffffu, s,  o);
        s2 += __shfl_xor_sync(0xffffffffu, s2, o);
    }
    __shared__ float sh[8];
    if ((t & 31) == 0) { sh[t >> 5] = s; sh[4 + (t >> 5)] = s2; }
    __syncthreads();
    s  = sh[0] + sh[1] + sh[2] + sh[3];
    s2 = sh[4] + sh[5] + sh[6] + sh[7];
    float mu  = s * (1.0f / DD);
    float var = fmaxf(s2 * (1.0f / DD) - mu * mu, 0.0f);
    float r   = rsqrtf(var + 1e-6f);
    __half2 u01 = ((const __half2*)(g_mmh + (size_t)row * NC))[2 * t];
    __half2 u23 = ((const __half2*)(g_mmh + (size_t)row * NC))[2 * t + 1];
    float2 u0 = __half22float2(u01), u1 = __half22float2(u23);
    __half2 h0 = __floats2half2_rn(u0.x * (f0.x - mu) * r, u0.y * (f0.y - mu) * r);
    __half2 h1 = __floats2half2_rn(u1.x * (f1.x - mu) * r, u1.y * (f1.y - mu) * r);
    ((__half2*)(g_xnh + (size_t)row * DD))[2 * t]     = h0;
    ((__half2*)(g_xnh + (size_t)row * DD))[2 * t + 1] = h1;
}

// ---------------------------------------------------------------------------
// Weight converts
// ---------------------------------------------------------------------------
__global__ void cvt_w_t(const float* __restrict__ W) {
    __shared__ float tbuf[32][33];
    int lx = threadIdx.x & 31, ly = threadIdx.x >> 5;
    int bx = blockIdx.x, by = blockIdx.y;
    int col = bx * 32 + lx;
#pragma unroll
    for (int i = 0; i < 32; i += 8)
        tbuf[ly + i][lx] = W[(size_t)(by * 32 + ly + i) * NC + col];
    __syncthreads();
    int ok = by * 32 + lx;
#pragma unroll
    for (int i = 0; i < 32; i += 8)
        g_wh[(size_t)(bx * 32 + ly + i) * DD + ok] = __float2half_rn(tbuf[lx][ly + i]);
}

__global__ void cvt_ow(const float* __restrict__ W) {
    int i = blockIdx.x * 256 + threadIdx.x;
    float4 v = ((const float4*)W)[i];
    __half2 h0 = __floats2half2_rn(v.x, v.y);
    __half2 h1 = __floats2half2_rn(v.z, v.w);
    ((__half2*)g_owh)[2 * i]     = h0;
    ((__half2*)g_owh)[2 * i + 1] = h1;
}

// ---------------------------------------------------------------------------
// fp16 mma GEMM1: 128x128, BK=64, 2-stage, one sync per chunk.
// Round 16: __launch_bounds__(256,3) -> ~84 regs -> 3 CTAs/SM (smem allows).
// ---------------------------------------------------------------------------
#define SAH   72
#define ASBH  (128 * SAH * 2)
#define GSMEMH (4 * ASBH)

__global__ __launch_bounds__(256, 3)
void gemm_h(const __half* __restrict__ A, const __half* __restrict__ Bm,
            __half* __restrict__ Ch, int Nn, int K) {
    extern __shared__ char smem[];
    uint32_t sAu = smem_u32(smem);
    uint32_t sBu = sAu + 2 * ASBH;

    int tid = threadIdx.x;
    int wid = tid >> 5, lane = tid & 31;
    int m0 = blockIdx.y * 128, n0 = blockIdx.x * 128;
    int wm = (wid & 1) * 64;
    int wn = (wid >> 1) * 32;

    float acc[4][4][4];
#pragma unroll
    for (int i = 0; i < 4; i++)
#pragma unroll
        for (int j = 0; j < 4; j++)
#pragma unroll
            for (int r = 0; r < 4; r++) acc[i][j][r] = 0.0f;

    const int NCH = K / 64;
    uint32_t aoff = ldm_off_h(lane, SAH);
    uint32_t boff = (uint32_t)(wn * SAH * 2) + ldm_off_b(lane, SAH);

    auto stageA = [&](int c, int s) {
#pragma unroll
        for (int i = 0; i < 4; i++) {
            int idx = tid + i * 256;
            int row = idx >> 3, seg = idx & 7;
            cp16(sAu + s * ASBH + (row * SAH + seg * 8) * 2,
                 A + (size_t)(m0 + row) * K + c * 64 + seg * 8);
        }
    };
    auto stageB = [&](int c, int s) {
#pragma unroll
        for (int i = 0; i < 4; i++) {
            int idx = tid + i * 256;
            int row = idx >> 3, seg = idx & 7;
            cp16(sBu + s * ASBH + (row * SAH + seg * 8) * 2,
                 Bm + (size_t)(n0 + row) * K + c * 64 + seg * 8);
        }
    };

    stageA(0, 0); stageB(0, 0); CP_COMMIT();

    for (int c = 0; c < NCH; c++) {
        int s = c & 1;
        CP_WAIT(0);
        __syncthreads();
        if (c + 1 < NCH) {
            stageA(c + 1, s ^ 1); stageB(c + 1, s ^ 1); CP_COMMIT();
        }

#pragma unroll
        for (int ks = 0; ks < 4; ks++) {
            uint32_t b01[4], b23[4];
            ldmA(b01, sBu + s * ASBH + boff + ks * 32);
            ldmA(b23, sBu + s * ASBH + boff + 16 * SAH * 2 + ks * 32);
#pragma unroll
            for (int im = 0; im < 4; im++) {
                uint32_t a[4];
                ldmA(a, sAu + s * ASBH + (uint32_t)((wm + im * 16) * SAH * 2 + ks * 32) + aoff);
                mma_f16(acc[im][0], a, b01[0], b01[1]);
                mma_f16(acc[im][1], a, b01[2], b01[3]);
                mma_f16(acc[im][2], a, b23[0], b23[1]);
                mma_f16(acc[im][3], a, b23[2], b23[3]);
            }
        }
    }

    int er = lane >> 2, ec = (lane & 3) * 2;
#pragma unroll
    for (int im = 0; im < 4; im++) {
#pragma unroll
        for (int in = 0; in < 4; in++) {
            int row = m0 + wm + im * 16 + er;
            int col = n0 + wn + in * 8 + ec;
#pragma unroll
            for (int h = 0; h < 2; h++) {
                float v0 = acc[im][in][2 * h + 0];
                float v1 = acc[im][in][2 * h + 1];
                int rr = row + 8 * h;
                *(uint32_t*)(Ch + (size_t)rr * Nn + col) = silu_h2(v0, v1);
            }
        }
    }
}

// ---------------------------------------------------------------------------
// fp16 mma GEMM2: out = o_input @ W^T + bias + x.  128x64 tiles (512 blocks
// -> ~2 full waves vs <1 wave at 128x128). 8 warps 4m x 2n, warp tile 32x32.
// ---------------------------------------------------------------------------
#define BSB2 (64 * SAH * 2)                // 9216 per stage
#define G2SMEM (2 * ASBH + 2 * BSB2)       // 55296

__global__ __launch_bounds__(256)
void gemm2_h(const __half* __restrict__ A, const __half* __restrict__ Bm,
             float* __restrict__ Cf, const float* __restrict__ bias,
             const float* __restrict__ xres) {
    extern __shared__ char smem[];
    uint32_t sAu = smem_u32(smem);
    uint32_t sBu = sAu + 2 * ASBH;

    int tid = threadIdx.x;
    int wid = tid >> 5, lane = tid & 31;
    int m0 = blockIdx.y * 128, n0 = blockIdx.x * 64;
    int wm = (wid & 3) * 32;
    int wn = (wid >> 2) * 32;

    float acc[2][4][4];
#pragma unroll
    for (int i = 0; i < 2; i++)
#pragma unroll
        for (int j = 0; j < 4; j++)
#pragma unroll
            for (int r = 0; r < 4; r++) acc[i][j][r] = 0.0f;

    uint32_t aoff = ldm_off_h(lane, SAH);
    uint32_t boff = (uint32_t)(wn * SAH * 2) + ldm_off_b(lane, SAH);

    auto stageA = [&](int c, int s) {
#pragma unroll
        for (int i = 0; i < 4; i++) {
            int idx = tid + i * 256;
            int row = idx >> 3, seg = idx & 7;
            cp16(sAu + s * ASBH + (row * SAH + seg * 8) * 2,
                 A + (size_t)(m0 + row) * DD + c * 64 + seg * 8);
        }
    };
    auto stageB = [&](int c, int s) {
#pragma unroll
        for (int i = 0; i < 2; i++) {
            int idx = tid + i * 256;          // 512 segs (64 rows x 8)
            int row = idx >> 3, seg = idx & 7;
            cp16(sBu + s * BSB2 + (row * SAH + seg * 8) * 2,
                 Bm + (size_t)(n0 + row) * DD + c * 64 + seg * 8);
        }
    };

    stageA(0, 0); stageB(0, 0); CP_COMMIT();

    for (int c = 0; c < 8; c++) {
        int s = c & 1;
        CP_WAIT(0);
        __syncthreads();
        if (c + 1 < 8) {
            stageA(c + 1, s ^ 1); stageB(c + 1, s ^ 1); CP_COMMIT();
        }

#pragma unroll
        for (int ks = 0; ks < 4; ks++) {
            uint32_t b01[4], b23[4];
            ldmA(b01, sBu + s * BSB2 + boff + ks * 32);
            ldmA(b23, sBu + s * BSB2 + boff + 16 * SAH * 2 + ks * 32);
#pragma unroll
            for (int im = 0; im < 2; im++) {
                uint32_t a[4];
                ldmA(a, sAu + s * ASBH + (uint32_t)((wm + im * 16) * SAH * 2 + ks * 32) + aoff);
                mma_f16(acc[im][0], a, b01[0], b01[1]);
                mma_f16(acc[im][1], a, b01[2], b01[3]);
                mma_f16(acc[im][2], a, b23[0], b23[1]);
                mma_f16(acc[im][3], a, b23[2], b23[3]);
            }
        }
    }

    int er = lane >> 2, ec = (lane & 3) * 2;
#pragma unroll
    for (int im = 0; im < 2; im++) {
#pragma unroll
        for (int in = 0; in < 4; in++) {
            int row = m0 + wm + im * 16 + er;
            int col = n0 + wn + in * 8 + ec;
#pragma unroll
            for (int h = 0; h < 2; h++) {
                int rr = row + 8 * h;
                float2 bi = *(const float2*)(bias + col);
                float2 xr = *(const float2*)(xres + (size_t)rr * DD + col);
                float2 o;
                o.x = acc[im][in][2 * h + 0] + bi.x + xr.x;
                o.y = acc[im][in][2 * h + 1] + bi.y + xr.y;
                *(float2*)(Cf + (size_t)rr * DD + col) = o;
            }
        }
    }
}

// ---------------------------------------------------------------------------
// Fused causal silu-attention (R15 proven): q-tile 64, 128-col KV macro-tiles,
// register-resident S, warp = (strip 16 rows, kv-half 64 cols), pair-reduced O.
// ---------------------------------------------------------------------------
#define SAT2  72
#define QT2B  (64 * SAT2 * 2)             // 9216
#define KV2B  (128 * SAT2 * 2)            // 18432
#define AOFF_K2 QT2B
#define AOFF_V2 (QT2B + 2 * KV2B)
#define ASMEM2  (QT2B + 4 * KV2B)         // 82944
#define RSTR  66

__global__ __launch_bounds__(256, 2)
void attn_mma() {
    extern __shared__ char smem[];
    uint32_t sbase = smem_u32(smem);
    uint32_t Qsu = sbase;

    int qt = (int)(gridDim.x - 1 - blockIdx.x);   // heavy blocks first
    int h = blockIdx.y, b = blockIdx.z;
    int tid = threadIdx.x;
    int wid = tid >> 5, lane = tid & 31;
    int strip = wid >> 1;
    int half  = wid & 1;
    int wm = strip * 16;
    const int qcol = 1024 + h * HD;
    const int kcol = 1536 + h * HD;
    const int vcol = 512 + h * HD;
    uint32_t aoffQ = ldm_off_h(lane, SAT2);
    uint32_t koff = (uint32_t)((half * 64) * SAT2 * 2) + ldm_off_b(lane, SAT2);

    int tl = lane & 7;
    int tmi = lane >> 3;
    int tkr = (tmi & 1) * 8 + tl;
    int tnc = (tmi >> 1) * 8;

    auto stageQ = [&]() {
#pragma unroll
        for (int i = 0; i < 2; i++) {
            int idx = tid + i * 256;
            int row = idx >> 3, seg = idx & 7;
            cp16(Qsu + (row * SAT2 + seg * 8) * 2,
                 g_mmh + (size_t)(b * NN + qt * 64 + row) * NC + qcol + seg * 8);
        }
    };
    auto stageKV2 = [&](int kt2, int s) {
        uint32_t kd = sbase + AOFF_K2 + s * KV2B;
        uint32_t vd = sbase + AOFF_V2 + s * KV2B;
#pragma unroll
        for (int i = 0; i < 4; i++) {
            int idx = tid + i * 256;
            int row = idx >> 3, seg = idx & 7;
            size_t gb = (size_t)(b * NN + kt2 * 128 + row) * NC;
            uint32_t so = (uint32_t)((row * SAT2 + seg * 8) * 2);
            cp16(kd + so, g_mmh + gb + kcol + seg * 8);
            cp16(vd + so, g_mmh + gb + vcol + seg * 8);
        }
    };

    float oacc[8][4];
#pragma unroll
    for (int j = 0; j < 8; j++)
#pragma unroll
        for (int r = 0; r < 4; r++) oacc[j][r] = 0.0f;

    uint32_t aq[4][4];
    const float inv_n = 1.0f / (float)NN;
    int er = lane >> 2, ec = (lane & 3) * 2;
    const int nkt2 = (qt + 2) >> 1;

    stageQ(); stageKV2(0, 0); CP_COMMIT();

    for (int kt2 = 0; kt2 < nkt2; kt2++) {
        int s = kt2 & 1;
        CP_WAIT(0);
        __syncthreads();

        if (kt2 + 1 < nkt2) { stageKV2(kt2 + 1, s ^ 1); CP_COMMIT(); }
        if (kt2 == 0) {
#pragma unroll
            for (int ks = 0; ks < 4; ks++)
                ldmA(aq[ks], Qsu + (uint32_t)(wm * SAT2 * 2 + ks * 32) + aoffQ);
        }

        uint32_t Ksu = sbase + AOFF_K2 + s * KV2B;
        uint32_t Vsu = sbase + AOFF_V2 + s * KV2B;

        // Phase 1: S[16 x 64] = Q_strip @ K_half^T (registers)
        float sacc[8][4];
#pragma unroll
        for (int j = 0; j < 8; j++)
#pragma unroll
            for (int r = 0; r < 4; r++) sacc[j][r] = 0.0f;
#pragma unroll
        for (int ks = 0; ks < 4; ks++) {
#pragma unroll
            for (int nb = 0; nb < 4; nb++) {
                uint32_t bk[4];
                ldmA(bk, Ksu + koff + (uint32_t)(nb * 16 * SAT2 * 2) + ks * 32);
                mma_f16(sacc[2 * nb + 0], aq[ks], bk[0], bk[1]);
                mma_f16(sacc[2 * nb + 1], aq[ks], bk[2], bk[3]);
            }
        }

        // mask + fast silu + pack (registers only)
        bool need_mask = (kt2 == nkt2 - 1);
        int ig0 = qt * 64 + wm + er;
        int jb = kt2 * 128 + half * 64;
        uint32_t sh2[8][2];
#pragma unroll
        for (int in = 0; in < 8; in++) {
            int jg = jb + in * 8 + ec;
            float v0 = sacc[in][0], v1 = sacc[in][1];
            float v2 = sacc[in][2], v3 = sacc[in][3];
            if (need_mask) {
                if (jg > ig0)         v0 = 0.0f;
                if (jg + 1 > ig0)     v1 = 0.0f;
                if (jg > ig0 + 8)     v2 = 0.0f;
                if (jg + 1 > ig0 + 8) v3 = 0.0f;
            }
            sh2[in][0] = silu_h2(v0, v1);
            sh2[in][1] = silu_h2(v2, v3);
        }

        // Phase 2: O_partial += S @ V_half (S A-frags = packed sacc)
#pragma unroll
        for (int ks = 0; ks < 4; ks++) {
            uint32_t a[4];
            a[0] = sh2[2 * ks + 0][0];
            a[1] = sh2[2 * ks + 0][1];
            a[2] = sh2[2 * ks + 1][0];
            a[3] = sh2[2 * ks + 1][1];
#pragma unroll
            for (int nb = 0; nb < 4; nb++) {
                uint32_t bv[4];
                ldmT(bv, Vsu + (uint32_t)(((half * 64 + ks * 16 + tkr) * SAT2 + nb * 16 + tnc) * 2));
                mma_f16(oacc[2 * nb + 0], a, bv[0], bv[1]);
                mma_f16(oacc[2 * nb + 1], a, bv[2], bv[3]);
            }
        }
    }

    // Pair reduction once per block
    __syncthreads();
    float* Rbuf = (float*)smem;
    if (half == 1) {
#pragma unroll
        for (int in = 0; in < 8; in++) {
#pragma unroll
            for (int hh = 0; hh < 2; hh++) {
                int row = wm + er + 8 * hh;
                int col = in * 8 + ec;
                float2 p; p.x = oacc[in][2 * hh + 0]; p.y = oacc[in][2 * hh + 1];
                *(float2*)(Rbuf + row * RSTR + col) = p;
            }
        }
    }
    __syncthreads();
    if (half == 0) {
#pragma unroll
        for (int in = 0; in < 8; in++) {
#pragma unroll
            for (int hh = 0; hh < 2; hh++) {
                int row = wm + er + 8 * hh;
                int col = in * 8 + ec;
                float2 p = *(const float2*)(Rbuf + row * RSTR + col);
                __half2 o = __floats2half2_rn(
                    (oacc[in][2 * hh + 0] + p.x) * inv_n,
                    (oacc[in][2 * hh + 1] + p.y) * inv_n);
                *(__half2*)(g_ath + (size_t)(b * NN + qt * 64 + row) * DD
                            + h * HD + col) = o;
            }
        }
    }
}

// ---------------------------------------------------------------------------
extern "C" void kernel_launch(void* const* d_in, const int* in_sizes, int n_in,
                              void* d_out, int out_size) {
    const float* x    = (const float*)d_in[0];
    const float* uvqk = (const float*)d_in[2];
    const float* ow   = (const float*)d_in[3];
    const float* ob   = (const float*)d_in[4];
    float* out = (float*)d_out;

    void *pxnh, *pmmh, *pwh, *powh;
    cudaGetSymbolAddress(&pxnh, g_xnh);
    cudaGetSymbolAddress(&pmmh, g_mmh);
    cudaGetSymbolAddress(&pwh,  g_wh);
    cudaGetSymbolAddress(&powh, g_owh);

    cudaFuncSetAttribute(gemm_h,  cudaFuncAttributeMaxDynamicSharedMemorySize, GSMEMH);
    cudaFuncSetAttribute(gemm2_h, cudaFuncAttributeMaxDynamicSharedMemorySize, G2SMEM);
    cudaFuncSetAttribute(attn_mma, cudaFuncAttributeMaxDynamicSharedMemorySize, ASMEM2);

    // 0. weight converts
    cvt_w_t<<<dim3(NC / 32, DD / 32), 256>>>(uvqk);
    cvt_ow<<<DD * DD / 1024, 256>>>(ow);
    // 1. xn = layernorm(x) -> half
    ln_kernel<<<RR, 128>>>(x);
    // 2. mm = silu(xn @ uvqk) -> half
    gemm_h<<<dim3(NC / 128, RR / 128), 256, GSMEMH>>>(
        (const __half*)pxnh, (const __half*)pwh, (__half*)pmmh, NC, DD);
    // 3. attention (q64 tiles, register-resident S)
    attn_mma<<<dim3(NN / 64, HH, BB), 256, ASMEM2>>>();
    // 4. o_input = u * layernorm(attn) -> half
    gated_ln_kernel<<<RR, 128>>>();
    // 5. out = o_input @ o_weight^T + bias + x -> fp32 (128x64 tiles)
    gemm2_h<<<dim3(DD / 64, RR / 128), 256, G2SMEM>>>(
        (const __half*)pxnh, (const __half*)powh, out, ob, x);
}

// round 17
// speedup vs baseline: 1.2378x; 1.2378x over previous
#include <cuda_runtime.h>
#include <cuda_fp16.h>
#include <cstdint>
#include <math.h>

// Problem constants
#define BB 4
#define NN 2048
#define DD 512
#define HH 8
#define HD 64
#define NC 2048
#define RR (BB*NN)

// Scratch (device globals; no allocation allowed)
__device__ __half g_xnh[(size_t)RR * DD];   // half: layernorm(x); later o_input
__device__ __half g_mmh[(size_t)RR * NC];   // half: silu(xn @ uvqk) [u|v|q|k]
__device__ __half g_wh [(size_t)NC * DD];   // half: uvqk transposed [n][k]
__device__ __half g_owh[(size_t)DD * DD];   // half: o_weight [n][k]
__device__ __half g_ath[(size_t)RR * DD];   // half attention output

// silu on a packed pair via tanh.approx.f16x2 (1 MUFU per 2 values)
__device__ __forceinline__ uint32_t silu_h2(float a, float b) {
    __half2 s = __floats2half2_rn(a, b);
    const __half2 hhalf = __floats2half2_rn(0.5f, 0.5f);
    __half2 hs = __hmul2(s, hhalf);
    uint32_t hsu = *(uint32_t*)&hs;
    uint32_t t;
    asm("tanh.approx.f16x2 %0, %1;" : "=r"(t) : "r"(hsu));
    __half2 th = *(__half2*)&t;
    __half2 sig = __hfma2(th, hhalf, hhalf);
    __half2 o = __hmul2(s, sig);
    return *(uint32_t*)&o;
}

__device__ __forceinline__ uint32_t smem_u32(const void* p) {
    uint32_t a;
    asm("{ .reg .u64 t; cvta.to.shared.u64 t, %1; cvt.u32.u64 %0, t; }"
        : "=r"(a) : "l"(p));
    return a;
}

__device__ __forceinline__ void ldmA(uint32_t* a, uint32_t addr) {
    asm volatile("ldmatrix.sync.aligned.m8n8.x4.shared.b16 {%0,%1,%2,%3}, [%4];"
                 : "=r"(a[0]), "=r"(a[1]), "=r"(a[2]), "=r"(a[3]) : "r"(addr));
}

__device__ __forceinline__ void ldmT(uint32_t* a, uint32_t addr) {
    asm volatile("ldmatrix.sync.aligned.m8n8.x4.trans.shared.b16 {%0,%1,%2,%3}, [%4];"
                 : "=r"(a[0]), "=r"(a[1]), "=r"(a[2]), "=r"(a[3]) : "r"(addr));
}

// fp16 mma, fp32 accumulate: D += A(16x16) * B(16x8)
__device__ __forceinline__ void mma_f16(float* d, const uint32_t* a,
                                        uint32_t b0, uint32_t b1) {
    asm volatile(
        "mma.sync.aligned.m16n8k16.row.col.f32.f16.f16.f32 "
        "{%0,%1,%2,%3},{%4,%5,%6,%7},{%8,%9},{%0,%1,%2,%3};"
        : "+f"(d[0]), "+f"(d[1]), "+f"(d[2]), "+f"(d[3])
        : "r"(a[0]), "r"(a[1]), "r"(a[2]), "r"(a[3]), "r"(b0), "r"(b1));
}

__device__ __forceinline__ void cp16(uint32_t dst, const void* src) {
    asm volatile("cp.async.cg.shared.global [%0], [%1], 16;" :: "r"(dst), "l"(src));
}
#define CP_COMMIT() asm volatile("cp.async.commit_group;" ::: "memory")
#define CP_WAIT(n)  asm volatile("cp.async.wait_group %0;" :: "n"(n) : "memory")

// ldmatrix-x4 per-lane byte offset for a 16x16-half A block, stride in halfs
__device__ __forceinline__ uint32_t ldm_off_h(int lane, int stride_halfs) {
    int r = (lane & 7) + ((lane >> 3) & 1) * 8;
    int c16 = (lane >> 4);
    return (uint32_t)(r * stride_halfs * 2 + c16 * 16);
}

// ldmatrix-x4 per-lane byte offset for B (K-major [n][k]): 2 n-frags x k16.
__device__ __forceinline__ uint32_t ldm_off_b(int lane, int stride_halfs) {
    int r = lane & 7;
    int m = lane >> 3;
    return (uint32_t)(((m >> 1) * 8 + r) * stride_halfs * 2 + (m & 1) * 16);
}

// ---------------------------------------------------------------------------
// LayerNorm: fp32 math, half output
// ---------------------------------------------------------------------------
__global__ void ln_kernel(const float* __restrict__ x) {
    int row = blockIdx.x;
    int t = threadIdx.x;
    float4 v = ((const float4*)(x + (size_t)row * DD))[t];
    float s  = v.x + v.y + v.z + v.w;
    float s2 = v.x*v.x + v.y*v.y + v.z*v.z + v.w*v.w;
#pragma unroll
    for (int o = 16; o > 0; o >>= 1) {
        s  += __shfl_xor_sync(0xffffffffu, s,  o);
        s2 += __shfl_xor_sync(0xffffffffu, s2, o);
    }
    __shared__ float sh[8];
    if ((t & 31) == 0) { sh[t >> 5] = s; sh[4 + (t >> 5)] = s2; }
    __syncthreads();
    s  = sh[0] + sh[1] + sh[2] + sh[3];
    s2 = sh[4] + sh[5] + sh[6] + sh[7];
    float mu  = s * (1.0f / DD);
    float var = fmaxf(s2 * (1.0f / DD) - mu * mu, 0.0f);
    float r   = rsqrtf(var + 1e-6f);
    __half2 h0 = __floats2half2_rn((v.x - mu) * r, (v.y - mu) * r);
    __half2 h1 = __floats2half2_rn((v.z - mu) * r, (v.w - mu) * r);
    ((__half2*)(g_xnh + (size_t)row * DD))[2 * t]     = h0;
    ((__half2*)(g_xnh + (size_t)row * DD))[2 * t + 1] = h1;
}

// Gated LN: reads half attention output, fp32 stats, half result
__global__ void gated_ln_kernel() {
    int row = blockIdx.x;
    int t = threadIdx.x;
    __half2 a01 = ((const __half2*)(g_ath + (size_t)row * DD))[2 * t];
    __half2 a23 = ((const __half2*)(g_ath + (size_t)row * DD))[2 * t + 1];
    float2 f0 = __half22float2(a01), f1 = __half22float2(a23);
    float s  = f0.x + f0.y + f1.x + f1.y;
    float s2 = f0.x*f0.x + f0.y*f0.y + f1.x*f1.x + f1.y*f1.y;
#pragma unroll
    for (int o = 16; o > 0; o >>= 1) {
        s  += __shfl_xor_sync(0xffffffffu, s,  o);
        s2 += __shfl_xor_sync(0xffffffffu, s2, o);
    }
    __shared__ float sh[8];
    if ((t & 31) == 0) { sh[t >> 5] = s; sh[4 + (t >> 5)] = s2; }
    __syncthreads();
    s  = sh[0] + sh[1] + sh[2] + sh[3];
    s2 = sh[4] + sh[5] + sh[6] + sh[7];
    float mu  = s * (1.0f / DD);
    float var = fmaxf(s2 * (1.0f / DD) - mu * mu, 0.0f);
    float r   = rsqrtf(var + 1e-6f);
    __half2 u01 = ((const __half2*)(g_mmh + (size_t)row * NC))[2 * t];
    __half2 u23 = ((const __half2*)(g_mmh + (size_t)row * NC))[2 * t + 1];
    float2 u0 = __half22float2(u01), u1 = __half22float2(u23);
    __half2 h0 = __floats2half2_rn(u0.x * (f0.x - mu) * r, u0.y * (f0.y - mu) * r);
    __half2 h1 = __floats2half2_rn(u1.x * (f1.x - mu) * r, u1.y * (f1.y - mu) * r);
    ((__half2*)(g_xnh + (size_t)row * DD))[2 * t]     = h0;
    ((__half2*)(g_xnh + (size_t)row * DD))[2 * t + 1] = h1;
}

// ---------------------------------------------------------------------------
// Weight converts
// ---------------------------------------------------------------------------
__global__ void cvt_w_t(const float* __restrict__ W) {
    __shared__ float tbuf[32][33];
    int lx = threadIdx.x & 31, ly = threadIdx.x >> 5;
    int bx = blockIdx.x, by = blockIdx.y;
    int col = bx * 32 + lx;
#pragma unroll
    for (int i = 0; i < 32; i += 8)
        tbuf[ly + i][lx] = W[(size_t)(by * 32 + ly + i) * NC + col];
    __syncthreads();
    int ok = by * 32 + lx;
#pragma unroll
    for (int i = 0; i < 32; i += 8)
        g_wh[(size_t)(bx * 32 + ly + i) * DD + ok] = __float2half_rn(tbuf[lx][ly + i]);
}

__global__ void cvt_ow(const float* __restrict__ W) {
    int i = blockIdx.x * 256 + threadIdx.x;
    float4 v = ((const float4*)W)[i];
    __half2 h0 = __floats2half2_rn(v.x, v.y);
    __half2 h1 = __floats2half2_rn(v.z, v.w);
    ((__half2*)g_owh)[2 * i]     = h0;
    ((__half2*)g_owh)[2 * i + 1] = h1;
}

// ---------------------------------------------------------------------------
// fp16 mma GEMM1: 128x128, BK=64, 2-stage, one sync per chunk.
// (R15 proven config: no maxBlocksPerSM cap -> ~117 regs, no spills)
// ---------------------------------------------------------------------------
#define SAH   72
#define ASBH  (128 * SAH * 2)
#define GSMEMH (4 * ASBH)

__global__ __launch_bounds__(256)
void gemm_h(const __half* __restrict__ A, const __half* __restrict__ Bm,
            __half* __restrict__ Ch, int Nn, int K) {
    extern __shared__ char smem[];
    uint32_t sAu = smem_u32(smem);
    uint32_t sBu = sAu + 2 * ASBH;

    int tid = threadIdx.x;
    int wid = tid >> 5, lane = tid & 31;
    int m0 = blockIdx.y * 128, n0 = blockIdx.x * 128;
    int wm = (wid & 1) * 64;
    int wn = (wid >> 1) * 32;

    float acc[4][4][4];
#pragma unroll
    for (int i = 0; i < 4; i++)
#pragma unroll
        for (int j = 0; j < 4; j++)
#pragma unroll
            for (int r = 0; r < 4; r++) acc[i][j][r] = 0.0f;

    const int NCH = K / 64;
    uint32_t aoff = ldm_off_h(lane, SAH);
    uint32_t boff = (uint32_t)(wn * SAH * 2) + ldm_off_b(lane, SAH);

    auto stageA = [&](int c, int s) {
#pragma unroll
        for (int i = 0; i < 4; i++) {
            int idx = tid + i * 256;
            int row = idx >> 3, seg = idx & 7;
            cp16(sAu + s * ASBH + (row * SAH + seg * 8) * 2,
                 A + (size_t)(m0 + row) * K + c * 64 + seg * 8);
        }
    };
    auto stageB = [&](int c, int s) {
#pragma unroll
        for (int i = 0; i < 4; i++) {
            int idx = tid + i * 256;
            int row = idx >> 3, seg = idx & 7;
            cp16(sBu + s * ASBH + (row * SAH + seg * 8) * 2,
                 Bm + (size_t)(n0 + row) * K + c * 64 + seg * 8);
        }
    };

    stageA(0, 0); stageB(0, 0); CP_COMMIT();

    for (int c = 0; c < NCH; c++) {
        int s = c & 1;
        CP_WAIT(0);
        __syncthreads();
        if (c + 1 < NCH) {
            stageA(c + 1, s ^ 1); stageB(c + 1, s ^ 1); CP_COMMIT();
        }

#pragma unroll
        for (int ks = 0; ks < 4; ks++) {
            uint32_t b01[4], b23[4];
            ldmA(b01, sBu + s * ASBH + boff + ks * 32);
            ldmA(b23, sBu + s * ASBH + boff + 16 * SAH * 2 + ks * 32);
#pragma unroll
            for (int im = 0; im < 4; im++) {
                uint32_t a[4];
                ldmA(a, sAu + s * ASBH + (uint32_t)((wm + im * 16) * SAH * 2 + ks * 32) + aoff);
                mma_f16(acc[im][0], a, b01[0], b01[1]);
                mma_f16(acc[im][1], a, b01[2], b01[3]);
                mma_f16(acc[im][2], a, b23[0], b23[1]);
                mma_f16(acc[im][3], a, b23[2], b23[3]);
            }
        }
    }

    int er = lane >> 2, ec = (lane & 3) * 2;
#pragma unroll
    for (int im = 0; im < 4; im++) {
#pragma unroll
        for (int in = 0; in < 4; in++) {
            int row = m0 + wm + im * 16 + er;
            int col = n0 + wn + in * 8 + ec;
#pragma unroll
            for (int h = 0; h < 2; h++) {
                float v0 = acc[im][in][2 * h + 0];
                float v1 = acc[im][in][2 * h + 1];
                int rr = row + 8 * h;
                *(uint32_t*)(Ch + (size_t)rr * Nn + col) = silu_h2(v0, v1);
            }
        }
    }
}

// ---------------------------------------------------------------------------
// fp16 mma GEMM2: out = o_input @ W^T + bias + x.  128x64 tiles (512 blocks
// -> ~2 full waves). 8 warps 4m x 2n, warp tile 32x32.
// ---------------------------------------------------------------------------
#define BSB2 (64 * SAH * 2)                // 9216 per stage
#define G2SMEM (2 * ASBH + 2 * BSB2)       // 55296

__global__ __launch_bounds__(256)
void gemm2_h(const __half* __restrict__ A, const __half* __restrict__ Bm,
             float* __restrict__ Cf, const float* __restrict__ bias,
             const float* __restrict__ xres) {
    extern __shared__ char smem[];
    uint32_t sAu = smem_u32(smem);
    uint32_t sBu = sAu + 2 * ASBH;

    int tid = threadIdx.x;
    int wid = tid >> 5, lane = tid & 31;
    int m0 = blockIdx.y * 128, n0 = blockIdx.x * 64;
    int wm = (wid & 3) * 32;
    int wn = (wid >> 2) * 32;

    float acc[2][4][4];
#pragma unroll
    for (int i = 0; i < 2; i++)
#pragma unroll
        for (int j = 0; j < 4; j++)
#pragma unroll
            for (int r = 0; r < 4; r++) acc[i][j][r] = 0.0f;

    uint32_t aoff = ldm_off_h(lane, SAH);
    uint32_t boff = (uint32_t)(wn * SAH * 2) + ldm_off_b(lane, SAH);

    auto stageA = [&](int c, int s) {
#pragma unroll
        for (int i = 0; i < 4; i++) {
            int idx = tid + i * 256;
            int row = idx >> 3, seg = idx & 7;
            cp16(sAu + s * ASBH + (row * SAH + seg * 8) * 2,
                 A + (size_t)(m0 + row) * DD + c * 64 + seg * 8);
        }
    };
    auto stageB = [&](int c, int s) {
#pragma unroll
        for (int i = 0; i < 2; i++) {
            int idx = tid + i * 256;
            int row = idx >> 3, seg = idx & 7;
            cp16(sBu + s * BSB2 + (row * SAH + seg * 8) * 2,
                 Bm + (size_t)(n0 + row) * DD + c * 64 + seg * 8);
        }
    };

    stageA(0, 0); stageB(0, 0); CP_COMMIT();

    for (int c = 0; c < 8; c++) {
        int s = c & 1;
        CP_WAIT(0);
        __syncthreads();
        if (c + 1 < 8) {
            stageA(c + 1, s ^ 1); stageB(c + 1, s ^ 1); CP_COMMIT();
        }

#pragma unroll
        for (int ks = 0; ks < 4; ks++) {
            uint32_t b01[4], b23[4];
            ldmA(b01, sBu + s * BSB2 + boff + ks * 32);
            ldmA(b23, sBu + s * BSB2 + boff + 16 * SAH * 2 + ks * 32);
#pragma unroll
            for (int im = 0; im < 2; im++) {
                uint32_t a[4];
                ldmA(a, sAu + s * ASBH + (uint32_t)((wm + im * 16) * SAH * 2 + ks * 32) + aoff);
                mma_f16(acc[im][0], a, b01[0], b01[1]);
                mma_f16(acc[im][1], a, b01[2], b01[3]);
                mma_f16(acc[im][2], a, b23[0], b23[1]);
                mma_f16(acc[im][3], a, b23[2], b23[3]);
            }
        }
    }

    int er = lane >> 2, ec = (lane & 3) * 2;
#pragma unroll
    for (int im = 0; im < 2; im++) {
#pragma unroll
        for (int in = 0; in < 4; in++) {
            int row = m0 + wm + im * 16 + er;
            int col = n0 + wn + in * 8 + ec;
#pragma unroll
            for (int h = 0; h < 2; h++) {
                int rr = row + 8 * h;
                float2 bi = *(const float2*)(bias + col);
                float2 xr = *(const float2*)(xres + (size_t)rr * DD + col);
                float2 o;
                o.x = acc[im][in][2 * h + 0] + bi.x + xr.x;
                o.y = acc[im][in][2 * h + 1] + bi.y + xr.y;
                *(float2*)(Cf + (size_t)rr * DD + col) = o;
            }
        }
    }
}

// ---------------------------------------------------------------------------
// Fused causal silu-attention (R15 proven): q-tile 64, 128-col KV macro-tiles,
// register-resident S, warp = (strip 16 rows, kv-half 64 cols), pair-reduced O.
// ---------------------------------------------------------------------------
#define SAT2  72
#define QT2B  (64 * SAT2 * 2)             // 9216
#define KV2B  (128 * SAT2 * 2)            // 18432
#define AOFF_K2 QT2B
#define AOFF_V2 (QT2B + 2 * KV2B)
#define ASMEM2  (QT2B + 4 * KV2B)         // 82944
#define RSTR  66

__global__ __launch_bounds__(256, 2)
void attn_mma() {
    extern __shared__ char smem[];
    uint32_t sbase = smem_u32(smem);
    uint32_t Qsu = sbase;

    int qt = (int)(gridDim.x - 1 - blockIdx.x);   // heavy blocks first
    int h = blockIdx.y, b = blockIdx.z;
    int tid = threadIdx.x;
    int wid = tid >> 5, lane = tid & 31;
    int strip = wid >> 1;
    int half  = wid & 1;
    int wm = strip * 16;
    const int qcol = 1024 + h * HD;
    const int kcol = 1536 + h * HD;
    const int vcol = 512 + h * HD;
    uint32_t aoffQ = ldm_off_h(lane, SAT2);
    uint32_t koff = (uint32_t)((half * 64) * SAT2 * 2) + ldm_off_b(lane, SAT2);

    int tl = lane & 7;
    int tmi = lane >> 3;
    int tkr = (tmi & 1) * 8 + tl;
    int tnc = (tmi >> 1) * 8;

    auto stageQ = [&]() {
#pragma unroll
        for (int i = 0; i < 2; i++) {
            int idx = tid + i * 256;
            int row = idx >> 3, seg = idx & 7;
            cp16(Qsu + (row * SAT2 + seg * 8) * 2,
                 g_mmh + (size_t)(b * NN + qt * 64 + row) * NC + qcol + seg * 8);
        }
    };
    auto stageKV2 = [&](int kt2, int s) {
        uint32_t kd = sbase + AOFF_K2 + s * KV2B;
        uint32_t vd = sbase + AOFF_V2 + s * KV2B;
#pragma unroll
        for (int i = 0; i < 4; i++) {
            int idx = tid + i * 256;
            int row = idx >> 3, seg = idx & 7;
            size_t gb = (size_t)(b * NN + kt2 * 128 + row) * NC;
            uint32_t so = (uint32_t)((row * SAT2 + seg * 8) * 2);
            cp16(kd + so, g_mmh + gb + kcol + seg * 8);
            cp16(vd + so, g_mmh + gb + vcol + seg * 8);
        }
    };

    float oacc[8][4];
#pragma unroll
    for (int j = 0; j < 8; j++)
#pragma unroll
        for (int r = 0; r < 4; r++) oacc[j][r] = 0.0f;

    uint32_t aq[4][4];
    const float inv_n = 1.0f / (float)NN;
    int er = lane >> 2, ec = (lane & 3) * 2;
    const int nkt2 = (qt + 2) >> 1;

    stageQ(); stageKV2(0, 0); CP_COMMIT();

    for (int kt2 = 0; kt2 < nkt2; kt2++) {
        int s = kt2 & 1;
        CP_WAIT(0);
        __syncthreads();

        if (kt2 + 1 < nkt2) { stageKV2(kt2 + 1, s ^ 1); CP_COMMIT(); }
        if (kt2 == 0) {
#pragma unroll
            for (int ks = 0; ks < 4; ks++)
                ldmA(aq[ks], Qsu + (uint32_t)(wm * SAT2 * 2 + ks * 32) + aoffQ);
        }

        uint32_t Ksu = sbase + AOFF_K2 + s * KV2B;
        uint32_t Vsu = sbase + AOFF_V2 + s * KV2B;

        // Phase 1: S[16 x 64] = Q_strip @ K_half^T (registers)
        float sacc[8][4];
#pragma unroll
        for (int j = 0; j < 8; j++)
#pragma unroll
            for (int r = 0; r < 4; r++) sacc[j][r] = 0.0f;
#pragma unroll
        for (int ks = 0; ks < 4; ks++) {
#pragma unroll
            for (int nb = 0; nb < 4; nb++) {
                uint32_t bk[4];
                ldmA(bk, Ksu + koff + (uint32_t)(nb * 16 * SAT2 * 2) + ks * 32);
                mma_f16(sacc[2 * nb + 0], aq[ks], bk[0], bk[1]);
                mma_f16(sacc[2 * nb + 1], aq[ks], bk[2], bk[3]);
            }
        }

        // mask + fast silu + pack (registers only)
        bool need_mask = (kt2 == nkt2 - 1);
        int ig0 = qt * 64 + wm + er;
        int jb = kt2 * 128 + half * 64;
        uint32_t sh2[8][2];
#pragma unroll
        for (int in = 0; in < 8; in++) {
            int jg = jb + in * 8 + ec;
            float v0 = sacc[in][0], v1 = sacc[in][1];
            float v2 = sacc[in][2], v3 = sacc[in][3];
            if (need_mask) {
                if (jg > ig0)         v0 = 0.0f;
                if (jg + 1 > ig0)     v1 = 0.0f;
                if (jg > ig0 + 8)     v2 = 0.0f;
                if (jg + 1 > ig0 + 8) v3 = 0.0f;
            }
            sh2[in][0] = silu_h2(v0, v1);
            sh2[in][1] = silu_h2(v2, v3);
        }

        // Phase 2: O_partial += S @ V_half (S A-frags = packed sacc)
#pragma unroll
        for (int ks = 0; ks < 4; ks++) {
            uint32_t a[4];
            a[0] = sh2[2 * ks + 0][0];
            a[1] = sh2[2 * ks + 0][1];
            a[2] = sh2[2 * ks + 1][0];
            a[3] = sh2[2 * ks + 1][1];
#pragma unroll
            for (int nb = 0; nb < 4; nb++) {
                uint32_t bv[4];
                ldmT(bv, Vsu + (uint32_t)(((half * 64 + ks * 16 + tkr) * SAT2 + nb * 16 + tnc) * 2));
                mma_f16(oacc[2 * nb + 0], a, bv[0], bv[1]);
                mma_f16(oacc[2 * nb + 1], a, bv[2], bv[3]);
            }
        }
    }

    // Pair reduction once per block
    __syncthreads();
    float* Rbuf = (float*)smem;
    if (half == 1) {
#pragma unroll
        for (int in = 0; in < 8; in++) {
#pragma unroll
            for (int hh = 0; hh < 2; hh++) {
                int row = wm + er + 8 * hh;
                int col = in * 8 + ec;
                float2 p; p.x = oacc[in][2 * hh + 0]; p.y = oacc[in][2 * hh + 1];
                *(float2*)(Rbuf + row * RSTR + col) = p;
            }
        }
    }
    __syncthreads();
    if (half == 0) {
#pragma unroll
        for (int in = 0; in < 8; in++) {
#pragma unroll
            for (int hh = 0; hh < 2; hh++) {
                int row = wm + er + 8 * hh;
                int col = in * 8 + ec;
                float2 p = *(const float2*)(Rbuf + row * RSTR + col);
                __half2 o = __floats2half2_rn(
                    (oacc[in][2 * hh + 0] + p.x) * inv_n,
                    (oacc[in][2 * hh + 1] + p.y) * inv_n);
                *(__half2*)(g_ath + (size_t)(b * NN + qt * 64 + row) * DD
                            + h * HD + col) = o;
            }
        }
    }
}

// ---------------------------------------------------------------------------
extern "C" void kernel_launch(void* const* d_in, const int* in_sizes, int n_in,
                              void* d_out, int out_size) {
    const float* x    = (const float*)d_in[0];
    const float* uvqk = (const float*)d_in[2];
    const float* ow   = (const float*)d_in[3];
    const float* ob   = (const float*)d_in[4];
    float* out = (float*)d_out;

    void *pxnh, *pmmh, *pwh, *powh;
    cudaGetSymbolAddress(&pxnh, g_xnh);
    cudaGetSymbolAddress(&pmmh, g_mmh);
    cudaGetSymbolAddress(&pwh,  g_wh);
    cudaGetSymbolAddress(&powh, g_owh);

    cudaFuncSetAttribute(gemm_h,  cudaFuncAttributeMaxDynamicSharedMemorySize, GSMEMH);
    cudaFuncSetAttribute(gemm2_h, cudaFuncAttributeMaxDynamicSharedMemorySize, G2SMEM);
    cudaFuncSetAttribute(attn_mma, cudaFuncAttributeMaxDynamicSharedMemorySize, ASMEM2);

    // 0. weight converts
    cvt_w_t<<<dim3(NC / 32, DD / 32), 256>>>(uvqk);
    cvt_ow<<<DD * DD / 1024, 256>>>(ow);
    // 1. xn = layernorm(x) -> half
    ln_kernel<<<RR, 128>>>(x);
    // 2. mm = silu(xn @ uvqk) -> half
    gemm_h<<<dim3(NC / 128, RR / 128), 256, GSMEMH>>>(
        (const __half*)pxnh, (const __half*)pwh, (__half*)pmmh, NC, DD);
    // 3. attention (q64 tiles, register-resident S)
    attn_mma<<<dim3(NN / 64, HH, BB), 256, ASMEM2>>>();
    // 4. o_input = u * layernorm(attn) -> half
    gated_ln_kernel<<<RR, 128>>>();
    // 5. out = o_input @ o_weight^T + bias + x -> fp32 (128x64 tiles)
    gemm2_h<<<dim3(DD / 64, RR / 128), 256, G2SMEM>>>(
        (const __half*)pxnh, (const __half*)powh, out, ob, x);
}